// round 1
// baseline (speedup 1.0000x reference)
#include <cuda_runtime.h>
#include <math.h>

#define C_IN   384
#define C_MID  1536
#define EMB_D  1024
#define BATCH  16
#define HW     1024
#define GROUPS 32
#define CPG    12      // channels per group = 384/32
#define EPSV   1e-5f

#define BM 128
#define BN 128
#define BK 8

// Scratch (device globals; allocation-free, graph-capture safe)
__device__ float g_h[(size_t)BATCH * C_MID * HW];      // 100.7 MB intermediate h
__device__ float g_embout[BATCH * 2 * C_MID];          // scale|shift per batch
__device__ float g_a[BATCH * C_IN];                    // per (b,c): rstd*gn_w
__device__ float g_bb[BATCH * C_IN];                   // per (b,c): gn_b - mu*rstd*gn_w

// ---------------------------------------------------------------------------
// Kernel 1: emb_out[b, j] = sum_k emb[b,k] * we[j,k] + be[j]
// One warp per j; each lane holds 8 float4 of the we row in registers and
// sweeps all 16 batches (emb is 64KB -> L1/L2 resident).
// grid = 3072/8 = 384 blocks, 256 threads.
// ---------------------------------------------------------------------------
__global__ void __launch_bounds__(256) emb_gemm(const float* __restrict__ emb,
                                                const float* __restrict__ we,
                                                const float* __restrict__ be) {
    int w = threadIdx.x >> 5, lane = threadIdx.x & 31;
    int j = blockIdx.x * 8 + w;
    const float4* wrow = (const float4*)(we + (size_t)j * EMB_D);
    float4 wv[8];
#pragma unroll
    for (int i = 0; i < 8; i++) wv[i] = wrow[lane + 32 * i];

#pragma unroll
    for (int b = 0; b < BATCH; b++) {
        const float4* er = (const float4*)(emb + (size_t)b * EMB_D);
        float acc = 0.f;
#pragma unroll
        for (int i = 0; i < 8; i++) {
            float4 ev = __ldg(&er[lane + 32 * i]);
            acc += wv[i].x * ev.x + wv[i].y * ev.y + wv[i].z * ev.z + wv[i].w * ev.w;
        }
#pragma unroll
        for (int off = 16; off; off >>= 1) acc += __shfl_xor_sync(0xffffffffu, acc, off);
        if (lane == 0) g_embout[b * (2 * C_MID) + j] = acc + be[j];
    }
}

// ---------------------------------------------------------------------------
// Kernel 2: GroupNorm stats -> per-channel affine.
// grid = (32 groups, 16 batches), 256 threads; reduce 12*1024 = 12288 floats.
// ---------------------------------------------------------------------------
__global__ void __launch_bounds__(256) gn_stats(const float* __restrict__ x,
                                                const float* __restrict__ gn_w,
                                                const float* __restrict__ gn_b) {
    int g = blockIdx.x, b = blockIdx.y;
    const float* xp = x + ((size_t)b * C_IN + (size_t)g * CPG) * HW;
    int t = threadIdx.x;
    const int N = CPG * HW;  // 12288

    float s = 0.f, ss = 0.f;
    for (int i = t * 4; i < N; i += 256 * 4) {
        float4 v = *(const float4*)(xp + i);
        s  += v.x + v.y + v.z + v.w;
        ss += v.x * v.x + v.y * v.y + v.z * v.z + v.w * v.w;
    }
#pragma unroll
    for (int off = 16; off; off >>= 1) {
        s  += __shfl_xor_sync(0xffffffffu, s, off);
        ss += __shfl_xor_sync(0xffffffffu, ss, off);
    }
    __shared__ float rs[8], rss[8];
    if ((t & 31) == 0) { rs[t >> 5] = s; rss[t >> 5] = ss; }
    __syncthreads();
    __shared__ float smu, srst;
    if (t == 0) {
        float S = 0.f, SS = 0.f;
#pragma unroll
        for (int i = 0; i < 8; i++) { S += rs[i]; SS += rss[i]; }
        float mu  = S / (float)N;
        float var = SS / (float)N - mu * mu;
        smu  = mu;
        srst = rsqrtf(var + EPSV);
    }
    __syncthreads();
    if (t < CPG) {
        int c = g * CPG + t;
        float a = srst * gn_w[c];
        g_a[b * C_IN + c]  = a;
        g_bb[b * C_IN + c] = gn_b[c] - smu * a;
    }
}

// ---------------------------------------------------------------------------
// Kernel 3: h = silu(W1 @ xn + b1) * (1+scale) + shift
// A = w1 (1536 x 384 row-major), B = xn built on the fly from x via (a,bb).
// 128x128 tile, BK=8, 256 threads, 8x8 microtile.
// grid = (12, 8, 16)
// ---------------------------------------------------------------------------
__global__ void __launch_bounds__(256) gemm1(const float* __restrict__ x,
                                             const float* __restrict__ w1,
                                             const float* __restrict__ b1) {
    __shared__ float As[BK][BM];
    __shared__ float Bs[BK][BN];

    int b  = blockIdx.z;
    int o0 = blockIdx.x * BM;
    int p0 = blockIdx.y * BN;
    int t  = threadIdx.x;
    int tx = t & 15, ty = t >> 4;

    const float* xb  = x + (size_t)b * C_IN * HW;
    const float* ga  = g_a  + b * C_IN;
    const float* gbb = g_bb + b * C_IN;

    int arow = t >> 1, akc = (t & 1) * 4;    // A tile: 128 x 8
    int bk   = t >> 5, bpc = (t & 31) * 4;   // B tile:   8 x 128

    float acc[8][8];
#pragma unroll
    for (int i = 0; i < 8; i++)
#pragma unroll
        for (int j = 0; j < 8; j++) acc[i][j] = 0.f;

    for (int k0 = 0; k0 < C_IN; k0 += BK) {
        float4 av = *(const float4*)(w1 + (size_t)(o0 + arow) * C_IN + k0 + akc);
        float a_c  = ga[k0 + bk];
        float bb_c = gbb[k0 + bk];
        float4 bv = *(const float4*)(xb + (size_t)(k0 + bk) * HW + p0 + bpc);
        bv.x = bv.x * a_c + bb_c;
        bv.y = bv.y * a_c + bb_c;
        bv.z = bv.z * a_c + bb_c;
        bv.w = bv.w * a_c + bb_c;

        __syncthreads();
        As[akc + 0][arow] = av.x;
        As[akc + 1][arow] = av.y;
        As[akc + 2][arow] = av.z;
        As[akc + 3][arow] = av.w;
        *(float4*)&Bs[bk][bpc] = bv;
        __syncthreads();

#pragma unroll
        for (int kk = 0; kk < BK; kk++) {
            float4 a0 = *(const float4*)&As[kk][ty * 8];
            float4 a1 = *(const float4*)&As[kk][ty * 8 + 4];
            float4 c0 = *(const float4*)&Bs[kk][tx * 8];
            float4 c1 = *(const float4*)&Bs[kk][tx * 8 + 4];
            float af[8] = {a0.x, a0.y, a0.z, a0.w, a1.x, a1.y, a1.z, a1.w};
            float bf[8] = {c0.x, c0.y, c0.z, c0.w, c1.x, c1.y, c1.z, c1.w};
#pragma unroll
            for (int i = 0; i < 8; i++)
#pragma unroll
                for (int j = 0; j < 8; j++) acc[i][j] += af[i] * bf[j];
        }
    }

    const float* sc = g_embout + b * (2 * C_MID);
#pragma unroll
    for (int i = 0; i < 8; i++) {
        int oo = o0 + ty * 8 + i;
        float bias  = b1[oo];
        float scale = 1.f + sc[oo];
        float shift = sc[C_MID + oo];
        float* hrow = g_h + ((size_t)b * C_MID + oo) * HW + p0 + tx * 8;
        float r[8];
#pragma unroll
        for (int j = 0; j < 8; j++) {
            float v = acc[i][j] + bias;
            float s = v / (1.f + __expf(-v));   // silu
            r[j] = s * scale + shift;
        }
        *(float4*)(hrow)     = make_float4(r[0], r[1], r[2], r[3]);
        *(float4*)(hrow + 4) = make_float4(r[4], r[5], r[6], r[7]);
    }
}

// ---------------------------------------------------------------------------
// Kernel 4: out = x + W2 @ h + b2
// A = w2 (384 x 1536 row-major), B = g_h. grid = (3, 8, 16)
// ---------------------------------------------------------------------------
__global__ void __launch_bounds__(256) gemm2(const float* __restrict__ x,
                                             const float* __restrict__ w2,
                                             const float* __restrict__ b2,
                                             float* __restrict__ out) {
    __shared__ float As[BK][BM];
    __shared__ float Bs[BK][BN];

    int b  = blockIdx.z;
    int o0 = blockIdx.x * BM;
    int p0 = blockIdx.y * BN;
    int t  = threadIdx.x;
    int tx = t & 15, ty = t >> 4;

    const float* hb = g_h + (size_t)b * C_MID * HW;

    int arow = t >> 1, akc = (t & 1) * 4;
    int bk   = t >> 5, bpc = (t & 31) * 4;

    float acc[8][8];
#pragma unroll
    for (int i = 0; i < 8; i++)
#pragma unroll
        for (int j = 0; j < 8; j++) acc[i][j] = 0.f;

    for (int k0 = 0; k0 < C_MID; k0 += BK) {
        float4 av = *(const float4*)(w2 + (size_t)(o0 + arow) * C_MID + k0 + akc);
        float4 bv = *(const float4*)(hb + (size_t)(k0 + bk) * HW + p0 + bpc);

        __syncthreads();
        As[akc + 0][arow] = av.x;
        As[akc + 1][arow] = av.y;
        As[akc + 2][arow] = av.z;
        As[akc + 3][arow] = av.w;
        *(float4*)&Bs[bk][bpc] = bv;
        __syncthreads();

#pragma unroll
        for (int kk = 0; kk < BK; kk++) {
            float4 a0 = *(const float4*)&As[kk][ty * 8];
            float4 a1 = *(const float4*)&As[kk][ty * 8 + 4];
            float4 c0 = *(const float4*)&Bs[kk][tx * 8];
            float4 c1 = *(const float4*)&Bs[kk][tx * 8 + 4];
            float af[8] = {a0.x, a0.y, a0.z, a0.w, a1.x, a1.y, a1.z, a1.w};
            float bf[8] = {c0.x, c0.y, c0.z, c0.w, c1.x, c1.y, c1.z, c1.w};
#pragma unroll
            for (int i = 0; i < 8; i++)
#pragma unroll
                for (int j = 0; j < 8; j++) acc[i][j] += af[i] * bf[j];
        }
    }

#pragma unroll
    for (int i = 0; i < 8; i++) {
        int oo = o0 + ty * 8 + i;
        float bias = b2[oo];
        size_t base = ((size_t)b * C_IN + oo) * HW + p0 + tx * 8;
        float4 x0 = *(const float4*)(x + base);
        float4 x1 = *(const float4*)(x + base + 4);
        float4 r0 = make_float4(x0.x + acc[i][0] + bias, x0.y + acc[i][1] + bias,
                                x0.z + acc[i][2] + bias, x0.w + acc[i][3] + bias);
        float4 r1 = make_float4(x1.x + acc[i][4] + bias, x1.y + acc[i][5] + bias,
                                x1.z + acc[i][6] + bias, x1.w + acc[i][7] + bias);
        *(float4*)(out + base)     = r0;
        *(float4*)(out + base + 4) = r1;
    }
}

// ---------------------------------------------------------------------------
extern "C" void kernel_launch(void* const* d_in, const int* in_sizes, int n_in,
                              void* d_out, int out_size) {
    const float* x    = (const float*)d_in[0];
    const float* emb  = (const float*)d_in[1];
    const float* gn_w = (const float*)d_in[2];
    const float* gn_b = (const float*)d_in[3];
    const float* w1   = (const float*)d_in[4];
    const float* b1   = (const float*)d_in[5];
    const float* we   = (const float*)d_in[6];
    const float* be   = (const float*)d_in[7];
    const float* w2   = (const float*)d_in[8];
    const float* b2   = (const float*)d_in[9];
    float* out = (float*)d_out;

    emb_gemm<<<(2 * C_MID) / 8, 256>>>(emb, we, be);
    gn_stats<<<dim3(GROUPS, BATCH), 256>>>(x, gn_w, gn_b);
    gemm1<<<dim3(C_MID / BM, HW / BN, BATCH), 256>>>(x, w1, b1);
    gemm2<<<dim3(C_IN / BM, HW / BN, BATCH), 256>>>(x, w2, b2, out);
}

// round 3
// speedup vs baseline: 2.2361x; 2.2361x over previous
#include <cuda_runtime.h>
#include <math.h>
#include <stdint.h>

#define C_IN   384
#define C_MID  1536
#define EMB_D  1024
#define BATCH  16
#define HW     1024
#define GROUPS 32
#define CPG    12
#define EPSV   1e-5f

#define BM 128
#define BN 128
#define BK 32
#define LDA 132               // BM + 4 pad (float4-aligned, breaks bank conflicts)
#define STAGE_F (BK * LDA)
#define SMEM_BYTES (4 * STAGE_F * 4)   // As[2] + Bs[2]

// ---------------- device scratch (allocation-free) ----------------
__device__ float g_h[(size_t)BATCH * C_MID * HW];   // intermediate h (100.7 MB)
__device__ float g_embout[BATCH * 2 * C_MID];
__device__ float g_a[BATCH * C_IN];
__device__ float g_bb[BATCH * C_IN];
__device__ float g_wt1[C_IN * C_MID];               // w1^T tf32-rounded: [K=384][M=1536]
__device__ float g_wt2[C_MID * C_IN];               // w2^T tf32-rounded: [K=1536][M=384]

// ---------------- helpers ----------------
__device__ __forceinline__ uint32_t f2tf(float f) {
    uint32_t u; asm("cvt.rna.tf32.f32 %0, %1;" : "=r"(u) : "f"(f)); return u;
}
__device__ __forceinline__ void mma8(float* c, const uint32_t* a, const uint32_t* b) {
    asm volatile(
        "mma.sync.aligned.m16n8k8.row.col.f32.tf32.tf32.f32 "
        "{%0,%1,%2,%3}, {%4,%5,%6,%7}, {%8,%9}, {%0,%1,%2,%3};\n"
        : "+f"(c[0]), "+f"(c[1]), "+f"(c[2]), "+f"(c[3])
        : "r"(a[0]), "r"(a[1]), "r"(a[2]), "r"(a[3]), "r"(b[0]), "r"(b[1]));
}
__device__ __forceinline__ void cpasync16(float* s, const float* g) {
    uint32_t sa = (uint32_t)__cvta_generic_to_shared(s);
    asm volatile("cp.async.cg.shared.global [%0], [%1], 16;\n" :: "r"(sa), "l"(g));
}

// ---------------------------------------------------------------------------
// emb GEMM
// ---------------------------------------------------------------------------
__global__ void __launch_bounds__(256) emb_gemm(const float* __restrict__ emb,
                                                const float* __restrict__ we,
                                                const float* __restrict__ be) {
    int w = threadIdx.x >> 5, lane = threadIdx.x & 31;
    int j = blockIdx.x * 8 + w;
    const float4* wrow = (const float4*)(we + (size_t)j * EMB_D);
    float4 wv[8];
#pragma unroll
    for (int i = 0; i < 8; i++) wv[i] = wrow[lane + 32 * i];
#pragma unroll
    for (int b = 0; b < BATCH; b++) {
        const float4* er = (const float4*)(emb + (size_t)b * EMB_D);
        float acc = 0.f;
#pragma unroll
        for (int i = 0; i < 8; i++) {
            float4 ev = __ldg(&er[lane + 32 * i]);
            acc += wv[i].x * ev.x + wv[i].y * ev.y + wv[i].z * ev.z + wv[i].w * ev.w;
        }
#pragma unroll
        for (int off = 16; off; off >>= 1) acc += __shfl_xor_sync(0xffffffffu, acc, off);
        if (lane == 0) g_embout[b * (2 * C_MID) + j] = acc + be[j];
    }
}

// ---------------------------------------------------------------------------
// GroupNorm stats -> per (b, c) affine
// ---------------------------------------------------------------------------
__global__ void __launch_bounds__(256) gn_stats(const float* __restrict__ x,
                                                const float* __restrict__ gn_w,
                                                const float* __restrict__ gn_b) {
    int g = blockIdx.x, b = blockIdx.y;
    const float* xp = x + ((size_t)b * C_IN + (size_t)g * CPG) * HW;
    int t = threadIdx.x;
    const int N = CPG * HW;

    float s = 0.f, ss = 0.f;
    for (int i = t * 4; i < N; i += 256 * 4) {
        float4 v = *(const float4*)(xp + i);
        s  += v.x + v.y + v.z + v.w;
        ss += v.x * v.x + v.y * v.y + v.z * v.z + v.w * v.w;
    }
#pragma unroll
    for (int off = 16; off; off >>= 1) {
        s  += __shfl_xor_sync(0xffffffffu, s, off);
        ss += __shfl_xor_sync(0xffffffffu, ss, off);
    }
    __shared__ float rs[8], rss[8];
    if ((t & 31) == 0) { rs[t >> 5] = s; rss[t >> 5] = ss; }
    __syncthreads();
    __shared__ float smu, srst;
    if (t == 0) {
        float S = 0.f, SS = 0.f;
#pragma unroll
        for (int i = 0; i < 8; i++) { S += rs[i]; SS += rss[i]; }
        float mu  = S / (float)N;
        float var = SS / (float)N - mu * mu;
        smu  = mu;
        srst = rsqrtf(var + EPSV);
    }
    __syncthreads();
    if (t < CPG) {
        int c = g * CPG + t;
        float a = srst * gn_w[c];
        g_a[b * C_IN + c]  = a;
        g_bb[b * C_IN + c] = gn_b[c] - smu * a;
    }
}

// ---------------------------------------------------------------------------
// Transpose M x K row-major -> K x M with tf32 (rna) rounding.
// ---------------------------------------------------------------------------
__global__ void transpose_rna(const float* __restrict__ w, float* __restrict__ wt,
                              int M, int K) {
    __shared__ float tile[32][33];
    int k0 = blockIdx.x * 32, m0 = blockIdx.y * 32;
    int tx = threadIdx.x, ty = threadIdx.y;   // 32 x 8
#pragma unroll
    for (int i = 0; i < 32; i += 8)
        tile[ty + i][tx] = w[(size_t)(m0 + ty + i) * K + k0 + tx];
    __syncthreads();
#pragma unroll
    for (int i = 0; i < 32; i += 8) {
        uint32_t u; float v = tile[tx][ty + i];
        asm("cvt.rna.tf32.f32 %0, %1;" : "=r"(u) : "f"(v));
        wt[(size_t)(k0 + ty + i) * M + m0 + tx] = __uint_as_float(u);
    }
}

// ---------------------------------------------------------------------------
// tf32 tensor-core GEMM, 128x128x32 tiles, 8 warps (2m x 4n), 64x32 warp tiles.
// EPI==1: B = xn (affine on fragment load), out = silu(.+b1)*(1+sc)+sh -> g_h
// EPI==2: B = g_h, out = x + (.+b2) -> outp
// ---------------------------------------------------------------------------
template <int KTOT, int MTOT, int EPI>
__global__ void __launch_bounds__(256, 2) mma_gemm(
    const float* __restrict__ wT,
    const float* __restrict__ Bsrc,
    const float* __restrict__ bias,
    const float* __restrict__ xres,
    float* __restrict__ outp)
{
    extern __shared__ float smm[];
    float* As = smm;                  // [2][BK][LDA]
    float* Bs = smm + 2 * STAGE_F;    // [2][BK][LDA]

    const int t = threadIdx.x;
    const int b = blockIdx.z;
    const int m0 = blockIdx.x * BM;
    const int p0 = blockIdx.y * BN;
    const int wid = t >> 5, lane = t & 31;
    const int gr = lane >> 2, tg = lane & 3;
    const int mw = (wid >> 2) * 64, nw = (wid & 3) * 32;

    const float* Bb = Bsrc + (size_t)b * KTOT * HW;
    const int ck = t >> 3;
    const int cc = (t & 7) * 16;

    const float* gA0 = wT + (size_t)ck * MTOT + m0 + cc;
    const float* gB0 = Bb + (size_t)ck * HW + p0 + cc;
    float* sA0 = As + ck * LDA + cc;
    float* sB0 = Bs + ck * LDA + cc;

    float acc[4][4][4];
#pragma unroll
    for (int i = 0; i < 4; i++)
#pragma unroll
        for (int j = 0; j < 4; j++)
#pragma unroll
            for (int q = 0; q < 4; q++) acc[i][j][q] = 0.f;

    const int S = KTOT / BK;

#pragma unroll
    for (int q = 0; q < 4; q++) {
        cpasync16(sA0 + q * 4, gA0 + q * 4);
        cpasync16(sB0 + q * 4, gB0 + q * 4);
    }
    asm volatile("cp.async.commit_group;\n");

    const float* ga  = g_a  + b * C_IN;
    const float* gbb = g_bb + b * C_IN;

    for (int s = 0; s < S; s++) {
        if (s + 1 < S) {
            int bufn = (s + 1) & 1;
            const float* gA = gA0 + (size_t)(s + 1) * BK * MTOT;
            const float* gB = gB0 + (size_t)(s + 1) * BK * HW;
            float* sA = sA0 + bufn * STAGE_F;
            float* sB = sB0 + bufn * STAGE_F;
#pragma unroll
            for (int q = 0; q < 4; q++) {
                cpasync16(sA + q * 4, gA + q * 4);
                cpasync16(sB + q * 4, gB + q * 4);
            }
            asm volatile("cp.async.commit_group;\n");
            asm volatile("cp.async.wait_group 1;\n");
        } else {
            asm volatile("cp.async.wait_group 0;\n");
        }
        __syncthreads();

        const float* A_ = As + (s & 1) * STAGE_F;
        const float* B_ = Bs + (s & 1) * STAGE_F;

#pragma unroll
        for (int kk = 0; kk < 4; kk++) {
            const int kA = kk * 8;
            uint32_t af[4][4];
#pragma unroll
            for (int mi = 0; mi < 4; mi++) {
                int mr = mw + mi * 16 + gr;
                af[mi][0] = __float_as_uint(A_[(kA + tg)     * LDA + mr]);
                af[mi][1] = __float_as_uint(A_[(kA + tg)     * LDA + mr + 8]);
                af[mi][2] = __float_as_uint(A_[(kA + tg + 4) * LDA + mr]);
                af[mi][3] = __float_as_uint(A_[(kA + tg + 4) * LDA + mr + 8]);
            }
            float aa0 = 0.f, bb0 = 0.f, aa1 = 0.f, bb1 = 0.f;
            if (EPI == 1) {
                int kg = s * BK + kA + tg;
                aa0 = ga[kg];     bb0 = gbb[kg];
                aa1 = ga[kg + 4]; bb1 = gbb[kg + 4];
            }
            uint32_t bf[4][2];
#pragma unroll
            for (int ni = 0; ni < 4; ni++) {
                int nc = nw + ni * 8 + gr;
                float v0 = B_[(kA + tg)     * LDA + nc];
                float v1 = B_[(kA + tg + 4) * LDA + nc];
                if (EPI == 1) { v0 = v0 * aa0 + bb0; v1 = v1 * aa1 + bb1; }
                bf[ni][0] = f2tf(v0);
                bf[ni][1] = f2tf(v1);
            }
#pragma unroll
            for (int mi = 0; mi < 4; mi++)
#pragma unroll
                for (int ni = 0; ni < 4; ni++)
                    mma8(acc[mi][ni], af[mi], bf[ni]);
        }
        __syncthreads();
    }

    if (EPI == 1) {
        const float* sc = g_embout + b * 2 * C_MID;
#pragma unroll
        for (int mi = 0; mi < 4; mi++) {
#pragma unroll
            for (int half = 0; half < 2; half++) {
                int r = m0 + mw + mi * 16 + gr + half * 8;
                float bi    = bias[r];
                float scale = 1.f + sc[r];
                float shift = sc[C_MID + r];
                float* orow = g_h + ((size_t)b * C_MID + r) * HW + p0 + nw;
#pragma unroll
                for (int ni = 0; ni < 4; ni++) {
                    float v0 = acc[mi][ni][half * 2]     + bi;
                    float v1 = acc[mi][ni][half * 2 + 1] + bi;
                    v0 = v0 / (1.f + __expf(-v0));
                    v1 = v1 / (1.f + __expf(-v1));
                    float2 o = make_float2(v0 * scale + shift, v1 * scale + shift);
                    *(float2*)(orow + ni * 8 + tg * 2) = o;
                }
            }
        }
    } else {
#pragma unroll
        for (int mi = 0; mi < 4; mi++) {
#pragma unroll
            for (int half = 0; half < 2; half++) {
                int r = m0 + mw + mi * 16 + gr + half * 8;
                float bi = bias[r];
                const float* xrow = xres + ((size_t)b * C_IN + r) * HW + p0 + nw;
                float* orow = outp + ((size_t)b * C_IN + r) * HW + p0 + nw;
#pragma unroll
                for (int ni = 0; ni < 4; ni++) {
                    float2 xv = *(const float2*)(xrow + ni * 8 + tg * 2);
                    float2 o = make_float2(xv.x + acc[mi][ni][half * 2]     + bi,
                                           xv.y + acc[mi][ni][half * 2 + 1] + bi);
                    *(float2*)(orow + ni * 8 + tg * 2) = o;
                }
            }
        }
    }
}

// ---------------------------------------------------------------------------
extern "C" void kernel_launch(void* const* d_in, const int* in_sizes, int n_in,
                              void* d_out, int out_size) {
    const float* x    = (const float*)d_in[0];
    const float* emb  = (const float*)d_in[1];
    const float* gn_w = (const float*)d_in[2];
    const float* gn_b = (const float*)d_in[3];
    const float* w1   = (const float*)d_in[4];
    const float* b1   = (const float*)d_in[5];
    const float* we   = (const float*)d_in[6];
    const float* be   = (const float*)d_in[7];
    const float* w2   = (const float*)d_in[8];
    const float* b2   = (const float*)d_in[9];
    float* out = (float*)d_out;

    float *hbuf, *wt1, *wt2;
    cudaGetSymbolAddress((void**)&hbuf, g_h);
    cudaGetSymbolAddress((void**)&wt1, g_wt1);
    cudaGetSymbolAddress((void**)&wt2, g_wt2);

    cudaFuncSetAttribute(mma_gemm<C_IN, C_MID, 1>,
                         cudaFuncAttributeMaxDynamicSharedMemorySize, SMEM_BYTES);
    cudaFuncSetAttribute(mma_gemm<C_MID, C_IN, 2>,
                         cudaFuncAttributeMaxDynamicSharedMemorySize, SMEM_BYTES);

    transpose_rna<<<dim3(C_IN / 32, C_MID / 32), dim3(32, 8)>>>(w1, wt1, C_MID, C_IN);
    transpose_rna<<<dim3(C_MID / 32, C_IN / 32), dim3(32, 8)>>>(w2, wt2, C_IN, C_MID);
    emb_gemm<<<(2 * C_MID) / 8, 256>>>(emb, we, be);
    gn_stats<<<dim3(GROUPS, BATCH), 256>>>(x, gn_w, gn_b);

    mma_gemm<C_IN, C_MID, 1><<<dim3(C_MID / BM, HW / BN, BATCH), 256, SMEM_BYTES>>>(
        wt1, x, b1, nullptr, nullptr);
    mma_gemm<C_MID, C_IN, 2><<<dim3(C_IN / BM, HW / BN, BATCH), 256, SMEM_BYTES>>>(
        wt2, hbuf, b2, x, out);
}

// round 6
// speedup vs baseline: 3.9241x; 1.7549x over previous
#include <cuda_runtime.h>
#include <math.h>
#include <stdint.h>

#define C_IN   384
#define C_MID  1536
#define EMB_D  1024
#define BATCH  16
#define HW     1024
#define GROUPS 32
#define CPG    12
#define EPSV   1e-5f

#define BM 128
#define BN 128
#define BK 32
#define LDB 136                         // B smem row pitch (floats): conflict-free frag loads
#define A_STG 4096                      // floats per A stage (128x32)
#define B_STG (BK * LDB)                // floats per B stage
#define STG_F (A_STG + B_STG)
#define NSTAGE 3
#define SMEMB (NSTAGE * STG_F * 4 + 1024)

// ---------------- device scratch (allocation-free) ----------------
__device__ float g_h[(size_t)BATCH * C_MID * HW];     // h, tf32-rounded
__device__ float g_xn[(size_t)BATCH * C_IN * HW];     // normalized x, tf32-rounded
__device__ float g_embout[BATCH * 2 * C_MID];
__device__ float g_a[BATCH * C_IN];
__device__ float g_bb[BATCH * C_IN];
__device__ float g_w1f[C_MID * C_IN];                 // w1 fragment-order, tf32
__device__ float g_w2f[C_IN * C_MID];                 // w2 fragment-order, tf32

// ---------------- helpers ----------------
__device__ __forceinline__ float tf32r(float f) {
    uint32_t u; asm("cvt.rna.tf32.f32 %0, %1;" : "=r"(u) : "f"(f));
    return __uint_as_float(u);
}
__device__ __forceinline__ void mma8(float* c, const uint32_t* a, const uint32_t* b) {
    asm volatile(
        "mma.sync.aligned.m16n8k8.row.col.f32.tf32.tf32.f32 "
        "{%0,%1,%2,%3}, {%4,%5,%6,%7}, {%8,%9}, {%0,%1,%2,%3};\n"
        : "+f"(c[0]), "+f"(c[1]), "+f"(c[2]), "+f"(c[3])
        : "r"(a[0]), "r"(a[1]), "r"(a[2]), "r"(a[3]), "r"(b[0]), "r"(b[1]));
}
__device__ __forceinline__ void cp16(float* s, const float* g) {
    uint32_t sa = (uint32_t)__cvta_generic_to_shared(s);
    asm volatile("cp.async.cg.shared.global [%0], [%1], 16;\n" :: "r"(sa), "l"(g));
}
#define CPCOMMIT() asm volatile("cp.async.commit_group;\n" ::: "memory")
#define CPWAIT(n)  asm volatile("cp.async.wait_group %0;\n" :: "n"(n) : "memory")

// ---------------------------------------------------------------------------
// Weight -> fragment-order transform (+ tf32 rna rounding).
// Region per (mblock mb, stage s): 4096 floats = [kk(4)][mt(8)][lane(32)][q(4)].
// Element (m,k): q encodes the mma reg slot, lane the owning thread.
// ---------------------------------------------------------------------------
__global__ void __launch_bounds__(256) wtrans(const float* __restrict__ w,
                                              float* __restrict__ wf,
                                              int M, int K) {
    int i = blockIdx.x * 256 + threadIdx.x;
    if (i >= M * K) return;
    int m = i / K, k = i % K;
    int S = K >> 5;
    int mb = m >> 7, s = k >> 5, kk = (k >> 3) & 3, mt = (m >> 4) & 7;
    int r = m & 15, c = k & 7;
    int q = (r >> 3) | ((c >> 2) << 1);
    int lane = (r & 7) * 4 + (c & 3);
    size_t dst = ((((size_t)(mb * S + s) * 4 + kk) * 8 + mt) * 32 + lane) * 4 + q;
    wf[dst] = tf32r(w[i]);
}

// ---------------------------------------------------------------------------
__global__ void __launch_bounds__(256) emb_gemm(const float* __restrict__ emb,
                                                const float* __restrict__ we,
                                                const float* __restrict__ be) {
    int w = threadIdx.x >> 5, lane = threadIdx.x & 31;
    int j = blockIdx.x * 8 + w;
    const float4* wrow = (const float4*)(we + (size_t)j * EMB_D);
    float4 wv[8];
#pragma unroll
    for (int i = 0; i < 8; i++) wv[i] = wrow[lane + 32 * i];
#pragma unroll
    for (int b = 0; b < BATCH; b++) {
        const float4* er = (const float4*)(emb + (size_t)b * EMB_D);
        float acc = 0.f;
#pragma unroll
        for (int i = 0; i < 8; i++) {
            float4 ev = __ldg(&er[lane + 32 * i]);
            acc += wv[i].x * ev.x + wv[i].y * ev.y + wv[i].z * ev.z + wv[i].w * ev.w;
        }
#pragma unroll
        for (int off = 16; off; off >>= 1) acc += __shfl_xor_sync(0xffffffffu, acc, off);
        if (lane == 0) g_embout[b * (2 * C_MID) + j] = acc + be[j];
    }
}

__global__ void __launch_bounds__(256) gn_stats(const float* __restrict__ x,
                                                const float* __restrict__ gn_w,
                                                const float* __restrict__ gn_b) {
    int g = blockIdx.x, b = blockIdx.y;
    const float* xp = x + ((size_t)b * C_IN + (size_t)g * CPG) * HW;
    int t = threadIdx.x;
    const int N = CPG * HW;
    float s = 0.f, ss = 0.f;
    for (int i = t * 4; i < N; i += 256 * 4) {
        float4 v = *(const float4*)(xp + i);
        s  += v.x + v.y + v.z + v.w;
        ss += v.x * v.x + v.y * v.y + v.z * v.z + v.w * v.w;
    }
#pragma unroll
    for (int off = 16; off; off >>= 1) {
        s  += __shfl_xor_sync(0xffffffffu, s, off);
        ss += __shfl_xor_sync(0xffffffffu, ss, off);
    }
    __shared__ float rs[8], rss[8];
    if ((t & 31) == 0) { rs[t >> 5] = s; rss[t >> 5] = ss; }
    __syncthreads();
    __shared__ float smu, srst;
    if (t == 0) {
        float S = 0.f, SS = 0.f;
#pragma unroll
        for (int i = 0; i < 8; i++) { S += rs[i]; SS += rss[i]; }
        float mu  = S / (float)N;
        float var = SS / (float)N - mu * mu;
        smu = mu; srst = rsqrtf(var + EPSV);
    }
    __syncthreads();
    if (t < CPG) {
        int c = g * CPG + t;
        float a = srst * gn_w[c];
        g_a[b * C_IN + c]  = a;
        g_bb[b * C_IN + c] = gn_b[c] - smu * a;
    }
}

// xn = tf32r(x * a + bb): one block per (c, b) row of 1024 floats.
__global__ void __launch_bounds__(256) xn_kernel(const float* __restrict__ x) {
    int c = blockIdx.x, b = blockIdx.y;
    float a  = g_a[b * C_IN + c];
    float bb = g_bb[b * C_IN + c];
    size_t base = ((size_t)b * C_IN + c) * HW + threadIdx.x * 4;
    float4 v = *(const float4*)(x + base);
    v.x = tf32r(v.x * a + bb); v.y = tf32r(v.y * a + bb);
    v.z = tf32r(v.z * a + bb); v.w = tf32r(v.w * a + bb);
    *(float4*)(g_xn + base) = v;
}

// ---------------------------------------------------------------------------
// tf32 mma.sync GEMM. A = fragment-order weights (pure cp.async, LDS.128 frags),
// B = pre-rounded activations (pure cp.async, conflict-free LDS.32 frags).
// 128x128 CTA tile, BK=32, 3-stage cp.async ring, 8 warps (2m x 4n).
// EPI==1: out = tf32r(silu(acc+b1)*(1+sc)+sh) -> g_h
// EPI==2: out = x + acc + b2 -> outp
// ---------------------------------------------------------------------------
template <int KTOT, int MTOT, int EPI>
__global__ void __launch_bounds__(256, 2) mma_gemm(
    const float* __restrict__ Wf,
    const float* __restrict__ Bsrc,
    const float* __restrict__ bias,
    const float* __restrict__ xres,
    float* __restrict__ outp)
{
    extern __shared__ float dsm[];
    float* sm = (float*)(((uintptr_t)dsm + 1023) & ~(uintptr_t)1023);

    const int t = threadIdx.x;
    const int b = blockIdx.z;
    const int m0 = blockIdx.x * BM;
    const int p0 = blockIdx.y * BN;
    const int wid = t >> 5, lane = t & 31;
    const int gr = lane >> 2, tg = lane & 3;
    const int mt4 = (wid >> 2) * 4;          // warp's A m-tile base (0 or 4)
    const int nw = (wid & 3) * 32;
    const int S = KTOT / BK;

    const float* Wb = Wf + (size_t)blockIdx.x * S * A_STG;
    const float* Bb = Bsrc + (size_t)b * KTOT * HW + p0;

    float acc[4][4][4];
#pragma unroll
    for (int i = 0; i < 4; i++)
#pragma unroll
        for (int j = 0; j < 4; j++)
#pragma unroll
            for (int q = 0; q < 4; q++) acc[i][j][q] = 0.f;

    // fill stage st into ring buffer st % NSTAGE
    auto fill = [&](int st) {
        float* sA = sm + (st % NSTAGE) * STG_F;
        float* sB = sA + A_STG;
        const float* gA = Wb + (size_t)st * A_STG;
#pragma unroll
        for (int it = 0; it < 4; it++)
            cp16(sA + t * 4 + it * 1024, gA + t * 4 + it * 1024);
        const int k0 = st * BK;
#pragma unroll
        for (int it = 0; it < 4; it++) {
            int idx = t + it * 256;          // 0..1023
            int k = idx >> 5, c4 = idx & 31;
            cp16(sB + k * LDB + c4 * 4, Bb + (size_t)(k0 + k) * HW + c4 * 4);
        }
        CPCOMMIT();
    };

    fill(0);
    if (S > 1) fill(1);

    for (int s = 0; s < S; s++) {
        if (s + 1 < S) CPWAIT(1); else CPWAIT(0);
        __syncthreads();
        if (s + 2 < S) fill(s + 2);

        const float* sA = sm + (s % NSTAGE) * STG_F;
        const float* sB = sA + A_STG;

#pragma unroll
        for (int kk = 0; kk < 4; kk++) {
            uint32_t af[4][4];
#pragma unroll
            for (int mi = 0; mi < 4; mi++) {
                const float4 v = *(const float4*)(sA + ((kk * 8 + mt4 + mi) * 32 + lane) * 4);
                af[mi][0] = __float_as_uint(v.x);
                af[mi][1] = __float_as_uint(v.y);
                af[mi][2] = __float_as_uint(v.z);
                af[mi][3] = __float_as_uint(v.w);
            }
            uint32_t bf[4][2];
#pragma unroll
            for (int ni = 0; ni < 4; ni++) {
                int nc = nw + ni * 8 + gr;
                bf[ni][0] = __float_as_uint(sB[(kk * 8 + tg)     * LDB + nc]);
                bf[ni][1] = __float_as_uint(sB[(kk * 8 + tg + 4) * LDB + nc]);
            }
#pragma unroll
            for (int mi = 0; mi < 4; mi++)
#pragma unroll
                for (int ni = 0; ni < 4; ni++)
                    mma8(acc[mi][ni], af[mi], bf[ni]);
        }
        __syncthreads();
    }

    // ---------------- epilogue ----------------
    const int mw = mt4 * 16;
    if (EPI == 1) {
        const float* sc = g_embout + b * 2 * C_MID;
#pragma unroll
        for (int mi = 0; mi < 4; mi++) {
#pragma unroll
            for (int half = 0; half < 2; half++) {
                int r = m0 + mw + mi * 16 + gr + half * 8;
                float bi    = bias[r];
                float scale = 1.f + sc[r];
                float shift = sc[C_MID + r];
                float* orow = g_h + ((size_t)b * C_MID + r) * HW + p0 + nw;
#pragma unroll
                for (int ni = 0; ni < 4; ni++) {
                    float v0 = acc[mi][ni][half * 2]     + bi;
                    float v1 = acc[mi][ni][half * 2 + 1] + bi;
                    v0 = v0 / (1.f + __expf(-v0));
                    v1 = v1 / (1.f + __expf(-v1));
                    float2 o = make_float2(tf32r(v0 * scale + shift),
                                           tf32r(v1 * scale + shift));
                    *(float2*)(orow + ni * 8 + tg * 2) = o;
                }
            }
        }
    } else {
#pragma unroll
        for (int mi = 0; mi < 4; mi++) {
#pragma unroll
            for (int half = 0; half < 2; half++) {
                int r = m0 + mw + mi * 16 + gr + half * 8;
                float bi = bias[r];
                const float* xrow = xres + ((size_t)b * C_IN + r) * HW + p0 + nw;
                float* orow = outp + ((size_t)b * C_IN + r) * HW + p0 + nw;
#pragma unroll
                for (int ni = 0; ni < 4; ni++) {
                    float2 xv = *(const float2*)(xrow + ni * 8 + tg * 2);
                    float2 o = make_float2(xv.x + acc[mi][ni][half * 2]     + bi,
                                           xv.y + acc[mi][ni][half * 2 + 1] + bi);
                    *(float2*)(orow + ni * 8 + tg * 2) = o;
                }
            }
        }
    }
}

// ---------------------------------------------------------------------------
extern "C" void kernel_launch(void* const* d_in, const int* in_sizes, int n_in,
                              void* d_out, int out_size) {
    const float* x    = (const float*)d_in[0];
    const float* emb  = (const float*)d_in[1];
    const float* gn_w = (const float*)d_in[2];
    const float* gn_b = (const float*)d_in[3];
    const float* w1   = (const float*)d_in[4];
    const float* b1   = (const float*)d_in[5];
    const float* we   = (const float*)d_in[6];
    const float* be   = (const float*)d_in[7];
    const float* w2   = (const float*)d_in[8];
    const float* b2   = (const float*)d_in[9];
    float* out = (float*)d_out;

    float *hbuf, *xnbuf, *w1f, *w2f;
    cudaGetSymbolAddress((void**)&hbuf, g_h);
    cudaGetSymbolAddress((void**)&xnbuf, g_xn);
    cudaGetSymbolAddress((void**)&w1f, g_w1f);
    cudaGetSymbolAddress((void**)&w2f, g_w2f);

    cudaFuncSetAttribute(mma_gemm<C_IN, C_MID, 1>,
                         cudaFuncAttributeMaxDynamicSharedMemorySize, SMEMB);
    cudaFuncSetAttribute(mma_gemm<C_MID, C_IN, 2>,
                         cudaFuncAttributeMaxDynamicSharedMemorySize, SMEMB);

    wtrans<<<(C_MID * C_IN + 255) / 256, 256>>>(w1, w1f, C_MID, C_IN);
    wtrans<<<(C_IN * C_MID + 255) / 256, 256>>>(w2, w2f, C_IN, C_MID);
    emb_gemm<<<(2 * C_MID) / 8, 256>>>(emb, we, be);
    gn_stats<<<dim3(GROUPS, BATCH), 256>>>(x, gn_w, gn_b);
    xn_kernel<<<dim3(C_IN, BATCH), 256>>>(x);

    mma_gemm<C_IN, C_MID, 1><<<dim3(C_MID / BM, HW / BN, BATCH), 256, SMEMB>>>(
        w1f, xnbuf, b1, nullptr, nullptr);
    mma_gemm<C_MID, C_IN, 2><<<dim3(C_IN / BM, HW / BN, BATCH), 256, SMEMB>>>(
        w2f, hbuf, b2, x, out);
}